// round 1
// baseline (speedup 1.0000x reference)
#include <cuda_runtime.h>
#include <stdint.h>

// out[i,j] = 2*x[i,j] + 5 - (i+j), x: [8192, 8192] fp32.
// Pure HBM-streaming kernel: float4 loads/stores, one vector per thread.

#define N_DIM 8192
#define M_DIM 8192
// float4s per row = 8192/4 = 2048 = 2^11
#define VEC_PER_ROW_LOG2 11
#define VEC_PER_ROW (1 << VEC_PER_ROW_LOG2)

__global__ __launch_bounds__(256) void fused_affine_outer_kernel(
    const float4* __restrict__ x, float4* __restrict__ out)
{
    // total vectors = 8192*2048 = 16,777,216 ; grid covers exactly.
    unsigned int v = blockIdx.x * 256u + threadIdx.x;
    unsigned int i = v >> VEC_PER_ROW_LOG2;          // row
    unsigned int j4 = (v & (VEC_PER_ROW - 1)) << 2;  // starting column of this float4

    float base = 5.0f - (float)(i + j4);             // 5 - (i + j) for lane 0

    float4 in = x[v];
    float4 o;
    o.x = fmaf(in.x, 2.0f, base);
    o.y = fmaf(in.y, 2.0f, base - 1.0f);
    o.z = fmaf(in.z, 2.0f, base - 2.0f);
    o.w = fmaf(in.w, 2.0f, base - 3.0f);
    out[v] = o;
}

extern "C" void kernel_launch(void* const* d_in, const int* in_sizes, int n_in,
                              void* d_out, int out_size)
{
    const float4* x = (const float4*)d_in[0];
    float4* out = (float4*)d_out;

    const unsigned int total_vec = (N_DIM * M_DIM) / 4;   // 16,777,216
    const unsigned int threads = 256;
    const unsigned int blocks = total_vec / threads;      // 65,536

    fused_affine_outer_kernel<<<blocks, threads>>>(x, out);
}

// round 2
// speedup vs baseline: 1.0031x; 1.0031x over previous
#include <cuda_runtime.h>
#include <stdint.h>

// out[i,j] = 2*x[i,j] + 5 - (i+j), x: [8192, 8192] fp32.
// HBM-streaming kernel: 4x front-batched float4 loads per thread (MLP=4),
// cache-streaming (evict-first) load/store hints.

#define N_DIM 8192
#define M_DIM 8192
#define VEC_PER_ROW_LOG2 11           // 8192/4 = 2048 float4 per row
#define VEC_PER_ROW (1 << VEC_PER_ROW_LOG2)
#define UNROLL 4

__global__ __launch_bounds__(256) void fused_affine_outer_kernel(
    const float4* __restrict__ x, float4* __restrict__ out)
{
    // Each block owns a contiguous chunk of UNROLL*256 vectors;
    // within the chunk, step k accesses are fully coalesced.
    unsigned int base = blockIdx.x * (256u * UNROLL) + threadIdx.x;

    float4 in[UNROLL];
#pragma unroll
    for (int k = 0; k < UNROLL; k++) {
        in[k] = __ldcs(&x[base + k * 256u]);
    }

#pragma unroll
    for (int k = 0; k < UNROLL; k++) {
        unsigned int v  = base + k * 256u;
        unsigned int i  = v >> VEC_PER_ROW_LOG2;          // row
        unsigned int j4 = (v & (VEC_PER_ROW - 1)) << 2;   // col of lane 0
        float b = 5.0f - (float)(i + j4);

        float4 o;
        o.x = fmaf(in[k].x, 2.0f, b);
        o.y = fmaf(in[k].y, 2.0f, b - 1.0f);
        o.z = fmaf(in[k].z, 2.0f, b - 2.0f);
        o.w = fmaf(in[k].w, 2.0f, b - 3.0f);
        __stcs(&out[v], o);
    }
}

extern "C" void kernel_launch(void* const* d_in, const int* in_sizes, int n_in,
                              void* d_out, int out_size)
{
    const float4* x = (const float4*)d_in[0];
    float4* out = (float4*)d_out;

    const unsigned int total_vec = (N_DIM * M_DIM) / 4;       // 16,777,216
    const unsigned int threads = 256;
    const unsigned int blocks = total_vec / (threads * UNROLL); // 16,384

    fused_affine_outer_kernel<<<blocks, threads>>>(x, out);
}